// round 6
// baseline (speedup 1.0000x reference)
#include <cuda_runtime.h>

typedef unsigned long long u64;

// x [16,3,256,256] f32, thetas[12], phis[3] -> out [16,1,128,128] f32
#define PPAIRS (16 * 128 * 64)   // 131072 threads, 2 patches each

// Per-layer monomial coefficients (CU ring (+CPhase for upper half) fused):
// state k (lower 16: w0=0, upper: w0=1) maps to PERM[k&15]|(k&16) with coef g_m*[L][k].
// Stored as u64 with the f32 value duplicated in both lanes.
__device__ u64 g_mR[3][32];
__device__ u64 g_mI[3][32];
__device__ float g_ph0[2];

__device__ __forceinline__ u64 dup_(float v) {
    unsigned u = __float_as_uint(v);
    return ((u64)u << 32) | u;
}

__global__ void prep_kernel(const float* __restrict__ thetas,
                            const float* __restrict__ phis) {
    if (threadIdx.x != 0) return;
    const int cb[4] = {8, 4, 2, 1};
    const int tb[4] = {4, 2, 1, 8};
    float f1r[12], f1i[12], f2r[12], f2i[12];
    for (int g = 0; g < 12; g++) {
        float s, c;
        sincosf(0.5f * thetas[g], &s, &c);
        f1r[g] = s;  f1i[g] = -c;    // f1 = -i e^{+i t/2} = sin - i cos
        f2r[g] = -s; f2i[g] = -c;    // f2 = -i e^{-i t/2} = -sin - i cos
    }
    for (int L = 0; L < 3; L++) {
        float ps, pc;
        sincosf(phis[L], &ps, &pc);
        for (int k = 0; k < 16; k++) {
            int m = k;
            float cr = 1.f, ci = 0.f;
            for (int w = 0; w < 4; w++) {
                if (m & cb[w]) {
                    int g = 4 * L + w;
                    float fr, fi;
                    if (m & tb[w]) { fr = f1r[g]; fi = f1i[g]; }
                    else           { fr = f2r[g]; fi = f2i[g]; }
                    float nr = cr * fr - ci * fi;
                    float ni = cr * fi + ci * fr;
                    cr = nr; ci = ni;
                    m ^= tb[w];
                }
            }
            g_mR[L][k] = dup_(cr);  g_mI[L][k] = dup_(ci);   // lower half (w0=0)
            float ur = cr, ui = ci;                          // upper half: + CPhase
            if (m & 8) {
                ur = cr * pc - ci * ps;
                ui = cr * ps + ci * pc;
            }
            g_mR[L][k + 16] = dup_(ur);  g_mI[L][k + 16] = dup_(ui);
        }
    }
    {
        float s, c;
        sincosf(phis[0], &s, &c);
        g_ph0[0] = c; g_ph0[1] = s;
    }
}

// ---- packed f32x2 helpers (lanes = 2 adjacent patches) ----
__device__ __forceinline__ u64 pk2(float lo, float hi) {
    u64 r; asm("mov.b64 %0,{%1,%2};" : "=l"(r) : "f"(lo), "f"(hi)); return r;
}
__device__ __forceinline__ u64 pk2b(float v) { return pk2(v, v); }
__device__ __forceinline__ void upk2(float& lo, float& hi, u64 v) {
    asm("mov.b64 {%0,%1},%2;" : "=f"(lo), "=f"(hi) : "l"(v));
}
__device__ __forceinline__ u64 fma2(u64 a, u64 b, u64 c) {
    u64 d; asm("fma.rn.f32x2 %0,%1,%2,%3;" : "=l"(d) : "l"(a), "l"(b), "l"(c)); return d;
}
__device__ __forceinline__ u64 mul2(u64 a, u64 b) {
    u64 d; asm("mul.rn.f32x2 %0,%1,%2;" : "=l"(d) : "l"(a), "l"(b)); return d;
}
__device__ __forceinline__ u64 neg2(u64 a) {
    const u64 SGN = 0x8000000080000000ULL;
    u64 d; asm("xor.b64 %0,%1,%2;" : "=l"(d) : "l"(a), "l"(SGN)); return d;
}

struct CS { u64 c, s; };
__device__ __forceinline__ CS cs2(float alo, float ahi) {
    float sl, cl, sh, ch;
    __sincosf(0.5f * alo, &sl, &cl);
    __sincosf(0.5f * ahi, &sh, &ch);
    CS r; r.c = pk2(cl, ch); r.s = pk2(sl, sh); return r;
}
struct CT { u64 c, t; };
__device__ __forceinline__ CT ct2(float alo, float ahi) {
    float sl, cl, sh, ch;
    __sincosf(0.5f * alo, &sl, &cl);
    __sincosf(0.5f * ahi, &sh, &ch);
    CT r; r.c = pk2(cl, ch);
    r.t = pk2(__fdividef(sl, cl), __fdividef(sh, ch));
    return r;
}

// Permutation of the CU ring (per 4-wire half-space); fixed point k=0 (coef==1).
// 15-cycle in application order:
__device__ __constant__ const int CYC[15] = {1,9,14,3,2,11,5,6,4,15,10,12,8,7,13};

// In-place monomial pass over 16 amps at offset o, using coef table layer La.
template <int La, int O>
__device__ __forceinline__ void mono_half(u64* sr, u64* si) {
    u64 tR = sr[O + 13], tI = si[O + 13];
#pragma unroll
    for (int ii = 13; ii >= 0; ii--) {
        const int s_ = CYC[ii], d_ = CYC[ii + 1];
        u64 cr_ = g_mR[La][O + s_], ci_ = g_mI[La][O + s_];
        u64 ar = sr[O + s_], ai = si[O + s_];
        sr[O + d_] = fma2(neg2(ci_), ai, mul2(cr_, ar));
        si[O + d_] = fma2(ci_, ar, mul2(cr_, ai));
    }
    {   // close the cycle: new[CYC[0]=1] = c_{13} * old[13]
        u64 cr_ = g_mR[La][O + 13], ci_ = g_mI[La][O + 13];
        sr[O + 1] = fma2(neg2(ci_), tI, mul2(cr_, tR));
        si[O + 1] = fma2(ci_, tR, mul2(cr_, tI));
    }
}

// Full 32-amp state: k = w0*16 + n, n = w1*8 + w2*4 + w3*2 + w4
__global__ void __launch_bounds__(128)
sim_kernel(const float* __restrict__ x, float* __restrict__ out) {
    int q   = blockIdx.x * 128 + threadIdx.x;
    int b   = q >> 13;
    int rem = q & 8191;
    int i   = rem >> 6;
    int jp  = rem & 63;

    const float4* __restrict__ x4 = (const float4*)x;

    u64 sr[32], si[32];

    // ================= Layer 0: product state (16 amps) =================
    {
        int base = ((b * 3 + 0) * 256 + 2 * i) * 64 + jp;
        float4 v0 = x4[base];
        float4 v1 = x4[base + 64];
        CS g0 = cs2(v0.x, v0.z), g1 = cs2(v0.y, v0.w);
        CS g2 = cs2(v1.x, v1.z), g3 = cs2(v1.y, v1.w);

        u64 INV2 = pk2b(0.70710678118654752f);
        u64 c0 = mul2(g0.c, INV2), s0 = mul2(g0.s, INV2);
        u64 ab[4] = { mul2(c0, g1.c), mul2(c0, g1.s), mul2(s0, g1.c), mul2(s0, g1.s) };
        u64 cd[4] = { mul2(g2.c, g3.c), mul2(g2.c, g3.s), mul2(g2.s, g3.c), mul2(g2.s, g3.s) };
#pragma unroll
        for (int n = 0; n < 16; n++) {
            u64 m = mul2(ab[n >> 2], cd[n & 3]);
            int pc = __popc(n) & 3;
            if (pc == 0)      { sr[n] = m;        si[n] = 0ULL;     }
            else if (pc == 1) { sr[n] = 0ULL;     si[n] = neg2(m);  }
            else if (pc == 2) { sr[n] = neg2(m);  si[n] = 0ULL;     }
            else              { sr[n] = 0ULL;     si[n] = m;        }
        }
    }

    // ---- Layer-0 CU ring as monomial on the 16-amp state ----
    mono_half<0, 0>(sr, si);

    // ---- Split into wire0 branches at CPhase-0 ----
    {
        u64 pr = pk2b(g_ph0[0]), pi = pk2b(g_ph0[1]);
        u64 npi = neg2(pi);
#pragma unroll
        for (int n = 0; n < 16; n++) {
            if (n & 8) {
                sr[16 + n] = fma2(npi, si[n], mul2(pr, sr[n]));
                si[16 + n] = fma2(pi,  sr[n], mul2(pr, si[n]));
            } else {
                sr[16 + n] = sr[n];
                si[16 + n] = si[n];
            }
        }
    }

    u64 Cacc = pk2b(1.0f);  // packed uniform RX cos scale (layers 1,2)

    // ================= Layers 1, 2 =================
#pragma unroll
    for (int L = 1; L < 3; L++) {
        int base = ((b * 3 + L) * 256 + 2 * i) * 64 + jp;
        float4 v0 = x4[base];
        float4 v1 = x4[base + 64];
        CT g[4] = { ct2(v0.x, v0.z), ct2(v0.y, v0.w),
                    ct2(v1.x, v1.z), ct2(v1.y, v1.w) };

        // RX via tan trick: RX/c = [[1,-it],[-it,1]]  (dense, 32 amps)
#pragma unroll
        for (int w = 0; w < 4; w++) {
            Cacc = mul2(Cacc, g[w].c);
            u64 t = g[w].t, nt = neg2(t);
            int m = 8 >> w;
#pragma unroll
            for (int k = 0; k < 32; k++) {
                if (!(k & m)) {
                    int k1 = k | m;
                    u64 a0r = sr[k],  a0i = si[k];
                    u64 a1r = sr[k1], a1i = si[k1];
                    sr[k]  = fma2(t,  a1i, a0r);
                    si[k]  = fma2(nt, a1r, a0i);
                    sr[k1] = fma2(t,  a0i, a1r);
                    si[k1] = fma2(nt, a0r, a1i);
                }
            }
        }
        // CU ring + CPhase as one monomial per half
        if (L == 1) {
            mono_half<1, 0>(sr, si);
            mono_half<1, 16>(sr, si);
        } else {
            mono_half<2, 0>(sr, si);
            mono_half<2, 16>(sr, si);
        }
    }

    // Final H on wire0 + <Z0>: ev = 2*C^2 * sum_n Re(conj(a_n) b_n)
    // (phi2's CPhase already folded into the layer-2 upper-half coefs)
    u64 acc = 0ULL;
#pragma unroll
    for (int n = 0; n < 16; n++) {
        acc = fma2(sr[n], sr[n + 16], acc);
        acc = fma2(si[n], si[n + 16], acc);
    }
    u64 C2 = mul2(Cacc, Cacc);
    acc = mul2(acc, mul2(C2, pk2b(2.0f)));

    float lo, hi;
    upk2(lo, hi, acc);
    ((float2*)out)[q] = make_float2(lo, hi);
}

extern "C" void kernel_launch(void* const* d_in, const int* in_sizes, int n_in,
                              void* d_out, int out_size) {
    const float* x      = (const float*)d_in[0];
    const float* thetas = (const float*)d_in[1];
    const float* phis   = (const float*)d_in[2];
    float* out = (float*)d_out;

    prep_kernel<<<1, 32>>>(thetas, phis);
    sim_kernel<<<PPAIRS / 128, 128>>>(x, out);
}

// round 8
// speedup vs baseline: 1.1391x; 1.1391x over previous
#include <cuda_runtime.h>

typedef unsigned long long u64;

// x [16,3,256,256] f32, thetas[12], phis[3] -> out [16,1,128,128] f32
#define PPAIRS (16 * 128 * 64)   // 131072 threads, 2 patches each

// ---- packed f32x2 helpers (lanes = 2 adjacent patches) ----
__device__ __forceinline__ u64 pk2(float lo, float hi) {
    u64 r; asm("mov.b64 %0,{%1,%2};" : "=l"(r) : "f"(lo), "f"(hi)); return r;
}
__device__ __forceinline__ u64 pk2b(float v) { return pk2(v, v); }
__device__ __forceinline__ void upk2(float& lo, float& hi, u64 v) {
    asm("mov.b64 {%0,%1},%2;" : "=f"(lo), "=f"(hi) : "l"(v));
}
__device__ __forceinline__ u64 fma2(u64 a, u64 b, u64 c) {
    u64 d; asm("fma.rn.f32x2 %0,%1,%2,%3;" : "=l"(d) : "l"(a), "l"(b), "l"(c)); return d;
}
__device__ __forceinline__ u64 mul2(u64 a, u64 b) {
    u64 d; asm("mul.rn.f32x2 %0,%1,%2;" : "=l"(d) : "l"(a), "l"(b)); return d;
}
__device__ __forceinline__ u64 neg2(u64 a) {
    const u64 SGN = 0x8000000080000000ULL;
    u64 d; asm("xor.b64 %0,%1,%2;" : "=l"(d) : "l"(a), "l"(SGN)); return d;
}

struct CS { u64 c, s; };
__device__ __forceinline__ CS cs2(float alo, float ahi) {
    float sl, cl, sh, ch;
    __sincosf(0.5f * alo, &sl, &cl);
    __sincosf(0.5f * ahi, &sh, &ch);
    CS r; r.c = pk2(cl, ch); r.s = pk2(sl, sh); return r;
}
struct CT { u64 c, t; };  // cos (uniform scale) + tan (butterfly)
__device__ __forceinline__ CT ct2(float alo, float ahi) {
    float sl, cl, sh, ch;
    __sincosf(0.5f * alo, &sl, &cl);
    __sincosf(0.5f * ahi, &sh, &ch);
    CT r; r.c = pk2(cl, ch);
    r.t = pk2(__fdividef(sl, cl), __fdividef(sh, ch));
    return r;
}

// CU butterfly using f1 = sin(t/2) - i cos(t/2);  f2 = -conj(f1).
// new0 = f1 * old1 ; new1 = f2 * old0.
// NB bits: within 4-wire space n = w1*8 + w2*4 + w3*2 + w4.
// Gate w: ctrl mask cm[w], tgt mask tm[w].
template <int NAMPS>
__device__ __forceinline__ void cu_gate(u64* sr, u64* si, int cmw, int tmw,
                                        float theta) {
    float s_, c_;
    __sincosf(0.5f * theta, &s_, &c_);
    u64 f1r = pk2b(s_), f1i = pk2b(-c_);
    u64 nf1r = neg2(f1r), nf1i = neg2(f1i);
#pragma unroll
    for (int k = 0; k < NAMPS; k++) {
        if ((k & cmw) && !(k & tmw)) {
            int k1 = k | tmw;
            u64 a0r = sr[k],  a0i = si[k];
            u64 a1r = sr[k1], a1i = si[k1];
            sr[k]  = fma2(nf1i, a1i, mul2(f1r, a1r));   // Re(f1*a1)
            si[k]  = fma2(f1i,  a1r, mul2(f1r, a1i));   // Im(f1*a1)
            sr[k1] = fma2(nf1i, a0i, mul2(nf1r, a0r));  // Re(f2*a0)
            si[k1] = fma2(nf1r, a0i, mul2(f1i, a0r));   // Im(f2*a0)
        }
    }
}

// Full 32-amp state: k = w0*16 + n
__global__ void __launch_bounds__(128, 3)
sim_kernel(const float* __restrict__ x,
           const float* __restrict__ thetas,
           const float* __restrict__ phis,
           float* __restrict__ out) {
    int q   = blockIdx.x * 128 + threadIdx.x;
    int b   = q >> 13;
    int rem = q & 8191;
    int i   = rem >> 6;
    int jp  = rem & 63;

    const float4* __restrict__ x4 = (const float4*)x;

    u64 sr[32], si[32];

    const int cm[4] = {8, 4, 2, 1};
    const int tm[4] = {4, 2, 1, 8};

    // ================= Layer 0: product state (16 amps) =================
    {
        int base = ((b * 3 + 0) * 256 + 2 * i) * 64 + jp;
        float4 v0 = x4[base];
        float4 v1 = x4[base + 64];
        CS g0 = cs2(v0.x, v0.z), g1 = cs2(v0.y, v0.w);
        CS g2 = cs2(v1.x, v1.z), g3 = cs2(v1.y, v1.w);

        u64 INV2 = pk2b(0.70710678118654752f);
        u64 c0 = mul2(g0.c, INV2), s0 = mul2(g0.s, INV2);
        u64 ab[4] = { mul2(c0, g1.c), mul2(c0, g1.s), mul2(s0, g1.c), mul2(s0, g1.s) };
        u64 cd[4] = { mul2(g2.c, g3.c), mul2(g2.c, g3.s), mul2(g2.s, g3.c), mul2(g2.s, g3.s) };
#pragma unroll
        for (int n = 0; n < 16; n++) {
            u64 m = mul2(ab[n >> 2], cd[n & 3]);
            int pc = __popc(n) & 3;
            if (pc == 0)      { sr[n] = m;        si[n] = 0ULL;     }
            else if (pc == 1) { sr[n] = 0ULL;     si[n] = neg2(m);  }
            else if (pc == 2) { sr[n] = neg2(m);  si[n] = 0ULL;     }
            else              { sr[n] = 0ULL;     si[n] = m;        }
        }
    }

    // ---- Layer-0 CU gates on the 16-amp state (wire0 untouched yet) ----
#pragma unroll
    for (int w = 0; w < 4; w++)
        cu_gate<16>(sr, si, cm[w], tm[w], thetas[w]);

    // ---- Split into wire0 branches at CPhase-0 ----
    {
        float ps_, pc_;
        __sincosf(phis[0], &ps_, &pc_);
        u64 pr = pk2b(pc_), pi = pk2b(ps_);
        u64 npi = neg2(pi);
#pragma unroll
        for (int n = 0; n < 16; n++) {
            if (n & 8) {
                sr[16 + n] = fma2(npi, si[n], mul2(pr, sr[n]));
                si[16 + n] = fma2(pi,  sr[n], mul2(pr, si[n]));
            } else {
                sr[16 + n] = sr[n];
                si[16 + n] = si[n];
            }
        }
    }

    u64 Cacc = pk2b(1.0f);  // packed uniform RX cos scale (layers 1,2)

    // ================= Layers 1, 2 =================
#pragma unroll
    for (int L = 1; L < 3; L++) {
        int base = ((b * 3 + L) * 256 + 2 * i) * 64 + jp;
        float4 v0 = x4[base];
        float4 v1 = x4[base + 64];
        CT g[4] = { ct2(v0.x, v0.z), ct2(v0.y, v0.w),
                    ct2(v1.x, v1.z), ct2(v1.y, v1.w) };

        // RX via tan trick: RX/c = [[1,-it],[-it,1]]  (dense, 32 amps)
#pragma unroll
        for (int w = 0; w < 4; w++) {
            Cacc = mul2(Cacc, g[w].c);
            u64 t = g[w].t, nt = neg2(t);
            int m = 8 >> w;
#pragma unroll
            for (int k = 0; k < 32; k++) {
                if (!(k & m)) {
                    int k1 = k | m;
                    u64 a0r = sr[k],  a0i = si[k];
                    u64 a1r = sr[k1], a1i = si[k1];
                    sr[k]  = fma2(t,  a1i, a0r);
                    si[k]  = fma2(nt, a1r, a0i);
                    sr[k1] = fma2(t,  a0i, a1r);
                    si[k1] = fma2(nt, a0r, a1i);
                }
            }
        }
        // CU gates (32 amps)
#pragma unroll
        for (int w = 0; w < 4; w++)
            cu_gate<32>(sr, si, cm[w], tm[w], thetas[4 * L + w]);

        // CPhase: apply in-state only for layer 1; layer 2 folds into reduce
        if (L == 1) {
            float ps_, pc_;
            __sincosf(phis[1], &ps_, &pc_);
            u64 pr = pk2b(pc_), pi = pk2b(ps_);
            u64 npi = neg2(pi);
#pragma unroll
            for (int k = 0; k < 32; k++) {
                if ((k & 24) == 24) {
                    u64 ar = sr[k], ai = si[k];
                    sr[k] = fma2(npi, ai, mul2(pr, ar));
                    si[k] = fma2(pi,  ar, mul2(pr, ai));
                }
            }
        }
    }

    // Final: ev = 2*C^2 * Re[ S0 + e^{i phi2} S1 ],
    //  S0 = sum_{n&8==0} conj(a_n) b_n,  S1 = sum_{n&8} conj(a_n) b_n
    u64 accR0 = 0ULL, accR1 = 0ULL, accI1 = 0ULL;
#pragma unroll
    for (int n = 0; n < 16; n++) {
        u64 ar = sr[n], ai = si[n];
        u64 br = sr[n + 16], bi = si[n + 16];
        if (n & 8) {
            accR1 = fma2(ar, br, accR1);
            accR1 = fma2(ai, bi, accR1);
            accI1 = fma2(ar, bi, accI1);
            accI1 = fma2(neg2(ai), br, accI1);
        } else {
            accR0 = fma2(ar, br, accR0);
            accR0 = fma2(ai, bi, accR0);
        }
    }
    {
        float ps_, pc_;
        __sincosf(phis[2], &ps_, &pc_);
        u64 cph = pk2b(pc_), sph = pk2b(ps_);
        u64 re = fma2(cph, accR1, accR0);
        re = fma2(neg2(sph), accI1, re);
        u64 C2 = mul2(Cacc, Cacc);
        re = mul2(re, mul2(C2, pk2b(2.0f)));

        float lo, hi;
        upk2(lo, hi, re);
        ((float2*)out)[q] = make_float2(lo, hi);
    }
}

extern "C" void kernel_launch(void* const* d_in, const int* in_sizes, int n_in,
                              void* d_out, int out_size) {
    const float* x      = (const float*)d_in[0];
    const float* thetas = (const float*)d_in[1];
    const float* phis   = (const float*)d_in[2];
    float* out = (float*)d_out;

    sim_kernel<<<PPAIRS / 128, 128>>>(x, thetas, phis, out);
}

// round 9
// speedup vs baseline: 1.2243x; 1.0748x over previous
#include <cuda_runtime.h>

typedef unsigned long long u64;

// x [16,3,256,256] f32, thetas[12], phis[3] -> out [16,1,128,128] f32
#define PPAIRS (16 * 128 * 64)   // 131072 threads, 2 patches each

// ---- packed f32x2 helpers (lanes = 2 adjacent patches) ----
__device__ __forceinline__ u64 pk2(float lo, float hi) {
    u64 r; asm("mov.b64 %0,{%1,%2};" : "=l"(r) : "f"(lo), "f"(hi)); return r;
}
__device__ __forceinline__ u64 pk2b(float v) { return pk2(v, v); }
__device__ __forceinline__ void upk2(float& lo, float& hi, u64 v) {
    asm("mov.b64 {%0,%1},%2;" : "=f"(lo), "=f"(hi) : "l"(v));
}
__device__ __forceinline__ u64 fma2(u64 a, u64 b, u64 c) {
    u64 d; asm("fma.rn.f32x2 %0,%1,%2,%3;" : "=l"(d) : "l"(a), "l"(b), "l"(c)); return d;
}
__device__ __forceinline__ u64 mul2(u64 a, u64 b) {
    u64 d; asm("mul.rn.f32x2 %0,%1,%2;" : "=l"(d) : "l"(a), "l"(b)); return d;
}
__device__ __forceinline__ u64 neg2(u64 a) {
    const u64 SGN = 0x8000000080000000ULL;
    u64 d; asm("xor.b64 %0,%1,%2;" : "=l"(d) : "l"(a), "l"(SGN)); return d;
}

struct CS { u64 c, s; };
__device__ __forceinline__ CS cs2(float alo, float ahi) {
    float sl, cl, sh, ch;
    __sincosf(0.5f * alo, &sl, &cl);
    __sincosf(0.5f * ahi, &sh, &ch);
    CS r; r.c = pk2(cl, ch); r.s = pk2(sl, sh); return r;
}
struct CT { u64 c, t; };  // cos (uniform scale) + tan (butterfly)
__device__ __forceinline__ CT ct2(float alo, float ahi) {
    float sl, cl, sh, ch;
    __sincosf(0.5f * alo, &sl, &cl);
    __sincosf(0.5f * ahi, &sh, &ch);
    CT r; r.c = pk2(cl, ch);
    r.t = pk2(__fdividef(sl, cl), __fdividef(sh, ch));
    return r;
}

// packed complex
struct Cp { u64 r, i; };
__device__ __forceinline__ Cp cmul(Cp a, Cp b) {
    Cp d;
    d.r = fma2(neg2(a.i), b.i, mul2(a.r, b.r));
    d.i = fma2(a.i, b.r, mul2(a.r, b.i));
    return d;
}

// CU-ring monomial: new[PERM[k]] = coef[k] * old[k] (per 4-wire half-space).
// PERM and coef structure derived from gates (c1,t2)(c2,t3)(c3,t4)(c4,t1),
// f1 = sin-icos (ctrl&tgt both 1 path), f2 = -conj(f1).
// k=0 is a fixed point with coef 1.
__device__ __forceinline__ void coef_table(const float* __restrict__ thetas,
                                           int L, Cp* c) {
    Cp f1[4], f2[4];
#pragma unroll
    for (int w = 0; w < 4; w++) {
        float s_, c_;
        __sincosf(0.5f * thetas[4 * L + w], &s_, &c_);
        f1[w].r = pk2b(s_);  f1[w].i = pk2b(-c_);
        f2[w].r = neg2(f1[w].r);  f2[w].i = f1[w].i;   // f2 = -conj(f1)
    }
    c[1]  = f2[3];
    c[3]  = f1[2];
    c[6]  = f1[1];
    c[12] = f1[0];
    c[2]  = cmul(f2[2], f2[3]);
    c[4]  = cmul(f2[1], c[2]);
    c[5]  = cmul(f2[1], f1[2]);
    c[7]  = cmul(f1[1], f2[3]);
    Cp E  = cmul(f2[0], f2[1]);
    c[9]  = cmul(E, f1[2]);
    Cp T  = cmul(f2[2], f1[3]);
    c[8]  = cmul(E, T);
    c[10] = cmul(f2[0], f1[1]);
    c[11] = cmul(c[10], f1[3]);
    c[13] = cmul(f1[0], f1[3]);
    c[14] = cmul(c[13], f2[2]);
    c[15] = cmul(f1[0], f1[2]);
}

__device__ __constant__ const int PERM[16] = {0,9,11,2,15,6,4,13,7,14,12,5,8,1,3,10};

// Apply monomial in place over 16 amps at offset O.
__device__ __forceinline__ void mono_apply(u64* sr, u64* si, int O, const Cp* c) {
    u64 tr[16], ti[16];
    tr[0] = sr[O]; ti[0] = si[O];
#pragma unroll
    for (int k = 1; k < 16; k++) {
        int m = PERM[k];
        u64 ar = sr[O + k], ai = si[O + k];
        u64 nci = neg2(c[k].i);
        tr[m] = fma2(nci,    ai, mul2(c[k].r, ar));
        ti[m] = fma2(c[k].i, ar, mul2(c[k].r, ai));
    }
#pragma unroll
    for (int k = 0; k < 16; k++) { sr[O + k] = tr[k]; si[O + k] = ti[k]; }
}

// Full 32-amp state: k = w0*16 + n,  n = w1*8 + w2*4 + w3*2 + w4
__global__ void __launch_bounds__(128, 3)
sim_kernel(const float* __restrict__ x,
           const float* __restrict__ thetas,
           const float* __restrict__ phis,
           float* __restrict__ out) {
    int q   = blockIdx.x * 128 + threadIdx.x;
    int b   = q >> 13;
    int rem = q & 8191;
    int i   = rem >> 6;
    int jp  = rem & 63;

    const float4* __restrict__ x4 = (const float4*)x;

    u64 sr[32], si[32];

    // ================= Layer 0: product state (16 amps) =================
    {
        int base = ((b * 3 + 0) * 256 + 2 * i) * 64 + jp;
        float4 v0 = x4[base];
        float4 v1 = x4[base + 64];
        CS g0 = cs2(v0.x, v0.z), g1 = cs2(v0.y, v0.w);
        CS g2 = cs2(v1.x, v1.z), g3 = cs2(v1.y, v1.w);

        u64 INV2 = pk2b(0.70710678118654752f);
        u64 c0 = mul2(g0.c, INV2), s0 = mul2(g0.s, INV2);
        u64 ab[4] = { mul2(c0, g1.c), mul2(c0, g1.s), mul2(s0, g1.c), mul2(s0, g1.s) };
        u64 cd[4] = { mul2(g2.c, g3.c), mul2(g2.c, g3.s), mul2(g2.s, g3.c), mul2(g2.s, g3.s) };
#pragma unroll
        for (int n = 0; n < 16; n++) {
            u64 m = mul2(ab[n >> 2], cd[n & 3]);
            int pc = __popc(n) & 3;
            if (pc == 0)      { sr[n] = m;        si[n] = 0ULL;     }
            else if (pc == 1) { sr[n] = 0ULL;     si[n] = neg2(m);  }
            else if (pc == 2) { sr[n] = neg2(m);  si[n] = 0ULL;     }
            else              { sr[n] = 0ULL;     si[n] = m;        }
        }
    }

    // ---- Layer-0 CU ring as monomial on the 16-amp state ----
    {
        Cp c[16];
        coef_table(thetas, 0, c);
        mono_apply(sr, si, 0, c);
    }

    // ---- Split into wire0 branches at CPhase-0 ----
    {
        float ps_, pc_;
        __sincosf(phis[0], &ps_, &pc_);
        u64 pr = pk2b(pc_), pi = pk2b(ps_);
        u64 npi = neg2(pi);
#pragma unroll
        for (int n = 0; n < 16; n++) {
            if (n & 8) {
                sr[16 + n] = fma2(npi, si[n], mul2(pr, sr[n]));
                si[16 + n] = fma2(pi,  sr[n], mul2(pr, si[n]));
            } else {
                sr[16 + n] = sr[n];
                si[16 + n] = si[n];
            }
        }
    }

    u64 Cacc = pk2b(1.0f);  // packed uniform RX cos scale (layers 1,2)

    // ================= Layers 1, 2 =================
#pragma unroll
    for (int L = 1; L < 3; L++) {
        int base = ((b * 3 + L) * 256 + 2 * i) * 64 + jp;
        float4 v0 = x4[base];
        float4 v1 = x4[base + 64];
        CT g[4] = { ct2(v0.x, v0.z), ct2(v0.y, v0.w),
                    ct2(v1.x, v1.z), ct2(v1.y, v1.w) };

        // RX via tan trick: RX/c = [[1,-it],[-it,1]]  (dense, 32 amps)
#pragma unroll
        for (int w = 0; w < 4; w++) {
            Cacc = mul2(Cacc, g[w].c);
            u64 t = g[w].t, nt = neg2(t);
            int m = 8 >> w;
#pragma unroll
            for (int k = 0; k < 32; k++) {
                if (!(k & m)) {
                    int k1 = k | m;
                    u64 a0r = sr[k],  a0i = si[k];
                    u64 a1r = sr[k1], a1i = si[k1];
                    sr[k]  = fma2(t,  a1i, a0r);
                    si[k]  = fma2(nt, a1r, a0i);
                    sr[k1] = fma2(t,  a0i, a1r);
                    si[k1] = fma2(nt, a0r, a1i);
                }
            }
        }

        // CU ring as one monomial per half (coefs shared across halves)
        {
            Cp c[16];
            coef_table(thetas, L, c);
            mono_apply(sr, si, 0,  c);
            mono_apply(sr, si, 16, c);
        }

        // CPhase: phase on (w0=1 & w1=1) -> upper half, n&8
        {
            float ps_, pc_;
            __sincosf(phis[L], &ps_, &pc_);
            u64 pr = pk2b(pc_), pi = pk2b(ps_);
            u64 npi = neg2(pi);
#pragma unroll
            for (int n = 8; n < 16; n++) {
                u64 ar = sr[16 + n], ai = si[16 + n];
                sr[16 + n] = fma2(npi, ai, mul2(pr, ar));
                si[16 + n] = fma2(pi,  ar, mul2(pr, ai));
            }
        }
    }

    // Final H on wire0 + <Z0>: ev = 2*C^2 * sum_n Re(conj(a_n) b_n)
    u64 acc = 0ULL;
#pragma unroll
    for (int n = 0; n < 16; n++) {
        acc = fma2(sr[n], sr[n + 16], acc);
        acc = fma2(si[n], si[n + 16], acc);
    }
    u64 C2 = mul2(Cacc, Cacc);
    acc = mul2(acc, mul2(C2, pk2b(2.0f)));

    float lo, hi;
    upk2(lo, hi, acc);
    ((float2*)out)[q] = make_float2(lo, hi);
}

extern "C" void kernel_launch(void* const* d_in, const int* in_sizes, int n_in,
                              void* d_out, int out_size) {
    const float* x      = (const float*)d_in[0];
    const float* thetas = (const float*)d_in[1];
    const float* phis   = (const float*)d_in[2];
    float* out = (float*)d_out;

    sim_kernel<<<PPAIRS / 128, 128>>>(x, thetas, phis, out);
}